// round 1
// baseline (speedup 1.0000x reference)
#include <cuda_runtime.h>
#include <stdint.h>

// MultiLevelHybridHashEncoding — instant-NGP style hash-grid encoding.
// B=1e6 points, D=3, 16 levels, 2 features/level.
// Levels 0..7: dense grid (res^3 <= 2^19 entries), levels 8..15: spatial hash (2^19 entries).
//
// Parallelization: one thread per (point, level). 16 consecutive threads = one point.
// Output (B, 16, 2) f32: thread writes one float2 -> warp stores 256 contiguous bytes.

#define NLEVELS 16

struct Params {
    const float2* tab[NLEVELS];
};

// floor(16 * 2^(l/3)) for l = 0..15, matching the numpy reference exactly.
__device__ __constant__ int c_res[NLEVELS] = {
    16, 20, 25, 32, 40, 50, 64, 80, 101, 128, 161, 203, 256, 322, 406, 512
};

__global__ __launch_bounds__(256, 8)
void hashenc_kernel(const float* __restrict__ x, Params p,
                    float2* __restrict__ out, int B)
{
    int tid = blockIdx.x * 256 + threadIdx.x;
    int b = tid >> 4;
    if (b >= B) return;
    int l = tid & 15;

    const int res  = c_res[l];
    const int res2 = res * res;
    const bool use_hash = (l >= 8);
    const float2* __restrict__ tab = p.tab[l];

    // x is (B,3) row-major; 16 sibling threads broadcast-load the same 12 bytes.
    const float px = __ldg(x + 3 * b + 0);
    const float py = __ldg(x + 3 * b + 1);
    const float pz = __ldg(x + 3 * b + 2);

    // xp = (x + 1) * (res/2) - 0.5 with the reference's exact f32 op order (no fma).
    const float sc = 0.5f * (float)res;
    const float xp = __fadd_rn(__fmul_rn(__fadd_rn(px, 1.0f), sc), -0.5f);
    const float yp = __fadd_rn(__fmul_rn(__fadd_rn(py, 1.0f), sc), -0.5f);
    const float zp = __fadd_rn(__fmul_rn(__fadd_rn(pz, 1.0f), sc), -0.5f);

    const float fx = floorf(xp), fy = floorf(yp), fz = floorf(zp);
    const int ix = (int)fx, iy = (int)fy, iz = (int)fz;
    const float tx = __fsub_rn(xp, fx);
    const float ty = __fsub_rn(yp, fy);
    const float tz = __fsub_rn(zp, fz);
    const float ux = __fsub_rn(1.0f, tx);
    const float uy = __fsub_rn(1.0f, ty);
    const float uz = __fsub_rn(1.0f, tz);

    float a0 = 0.0f, a1 = 0.0f;

    // CORNERS[i] = ((i>>2)&1, (i>>1)&1, i&1) per np.meshgrid('ij').
    #pragma unroll
    for (int ci = 0; ci < 8; ++ci) {
        const int ox = (ci >> 2) & 1;
        const int oy = (ci >> 1) & 1;
        const int oz = ci & 1;
        const int cx = ix + ox;
        const int cy = iy + oy;
        const int cz = iz + oz;

        const bool valid = ((unsigned)cx < (unsigned)res) &
                           ((unsigned)cy < (unsigned)res) &
                           ((unsigned)cz < (unsigned)res);
        if (valid) {
            // trilinear weight: prod over dims in order d0,d1,d2 (matches jnp.prod)
            const float w = __fmul_rn(__fmul_rn(ox ? tx : ux, oy ? ty : uy),
                                      oz ? tz : uz);

            // Branch-free index select (keeps lanes 0-7 / 8-15 converged).
            unsigned hidx = ((unsigned)cx)
                          ^ ((unsigned)cy * 2654435761u)
                          ^ ((unsigned)cz * 805459861u);
            hidx &= 0x7FFFFu;                       // % 2^19
            const unsigned didx = (unsigned)(cx + cy * res + cz * res2);
            const unsigned idx = use_hash ? hidx : didx;

            const float2 e = __ldg(&tab[idx]);
            a0 = fmaf(e.x, w, a0);
            a1 = fmaf(e.y, w, a1);
        }
    }

    out[(size_t)b * NLEVELS + l] = make_float2(a0, a1);
}

extern "C" void kernel_launch(void* const* d_in, const int* in_sizes, int n_in,
                              void* d_out, int out_size)
{
    const float* x = (const float*)d_in[0];
    Params p;
    #pragma unroll
    for (int l = 0; l < NLEVELS; ++l) {
        p.tab[l] = (const float2*)d_in[1 + l];
    }
    const int B = in_sizes[0] / 3;
    const int total = B * NLEVELS;
    const int blocks = (total + 255) / 256;
    hashenc_kernel<<<blocks, 256>>>(x, p, (float2*)d_out, B);
}